// round 1
// baseline (speedup 1.0000x reference)
#include <cuda_runtime.h>
#include <math.h>

// Problem dims (fixed by setup_inputs)
#define NREF 128
#define NSRC 128
#define NPTS 256
#define FD   256

// -------- device scratch (no allocations allowed) --------
__device__ float g_ptsn[NPTS * 3];
__device__ float g_sq[NPTS];
__device__ float g_dist[NREF * NSRC];
__device__ float g_feat[NREF * NSRC];
__device__ float g_rowmax_d[NREF];
__device__ int   g_rowarg_d[NREF];
__device__ float g_rowmax_f[NREF];
__device__ int   g_rowarg_f[NREF];
__device__ float g_geo[512];
__device__ float g_h1[256];

// orderable uint mapping: ascending uint <=> ascending float
__device__ __forceinline__ unsigned int f2o(float f) {
    unsigned int u = __float_as_uint(f);
    return (u & 0x80000000u) ? ~u : (u | 0x80000000u);
}

// composite sort key: descending value, ascending index (stable argsort of -v).
// We return the bitwise complement so an ASCENDING sort yields that order.
__device__ __forceinline__ unsigned long long sort_key(float v, int idx) {
    unsigned long long K =
        ((unsigned long long)f2o(v) << 32) | (unsigned long long)(255 - idx);
    return ~K;
}

// ================= K1: normalize points =================
// 1 block, 256 threads. Transform src half, joint centroid, max-norm scale.
__global__ void k_normalize(const float* __restrict__ pts,
                            const float* __restrict__ trans) {
    __shared__ float rx[256], ry[256], rz[256];
    __shared__ float cx, cy, cz, mfac;
    int t = threadIdx.x;
    float px = pts[t * 3 + 0];
    float py = pts[t * 3 + 1];
    float pz = pts[t * 3 + 2];
    if (t >= NREF) {
        // src @ R^T + t  with R = trans[:3,:3], translation trans[:3,3]
        float x = trans[0] * px + trans[1] * py + trans[2]  * pz + trans[3];
        float y = trans[4] * px + trans[5] * py + trans[6]  * pz + trans[7];
        float z = trans[8] * px + trans[9] * py + trans[10] * pz + trans[11];
        px = x; py = y; pz = z;
    }
    rx[t] = px; ry[t] = py; rz[t] = pz;
    __syncthreads();
    for (int s = 128; s > 0; s >>= 1) {
        if (t < s) { rx[t] += rx[t + s]; ry[t] += ry[t + s]; rz[t] += rz[t + s]; }
        __syncthreads();
    }
    if (t == 0) { cx = rx[0] / 256.0f; cy = ry[0] / 256.0f; cz = rz[0] / 256.0f; }
    __syncthreads();
    px -= cx; py -= cy; pz -= cz;
    float sq = px * px + py * py + pz * pz;
    rx[t] = sq;
    __syncthreads();
    for (int s = 128; s > 0; s >>= 1) {
        if (t < s) rx[t] = fmaxf(rx[t], rx[t + s]);
        __syncthreads();
    }
    if (t == 0) mfac = sqrtf(rx[0]);
    __syncthreads();
    px /= mfac; py /= mfac; pz /= mfac;
    g_ptsn[t * 3 + 0] = px;
    g_ptsn[t * 3 + 1] = py;
    g_ptsn[t * 3 + 2] = pz;
    g_sq[t] = px * px + py * py + pz * pz;
}

// ================= K2: per-row dist + feat matrices + row argmax =============
// grid 128 (one block per ref row i), 128 threads (one per src col j)
__global__ void k_rows(const float* __restrict__ ref_f,
                       const float* __restrict__ src_f) {
    int i = blockIdx.x;
    int j = threadIdx.x;
    __shared__ __align__(16) float sref[FD];
    __shared__ float sv[128];
    __shared__ int   si[128];

    sref[j]       = ref_f[i * FD + j];
    sref[j + 128] = ref_f[i * FD + 128 + j];
    __syncthreads();

    // --- dist entry ---
    float rx = g_ptsn[i * 3 + 0], ry = g_ptsn[i * 3 + 1], rz = g_ptsn[i * 3 + 2];
    int sjp = NREF + j;
    float sx = g_ptsn[sjp * 3 + 0], sy = g_ptsn[sjp * 3 + 1], sz = g_ptsn[sjp * 3 + 2];
    float d = g_sq[i] + g_sq[sjp] - 2.0f * (rx * sx + ry * sy + rz * sz);
    d = fmaxf(d, 0.0f);
    float e = expf(-d);
    g_dist[i * 128 + j] = e;

    // --- feat entry: dot(ref_i, src_j), K=256 ---
    const float4* s4 = reinterpret_cast<const float4*>(src_f + (size_t)j * FD);
    float acc = 0.0f;
#pragma unroll 8
    for (int k = 0; k < FD / 4; k++) {
        float4 v = s4[k];
        float4 r = *reinterpret_cast<const float4*>(&sref[4 * k]);
        acc += r.x * v.x + r.y * v.y + r.z * v.z + r.w * v.w;
    }
    g_feat[i * 128 + j] = acc;

    // --- row argmax (first occurrence) for dist ---
    sv[j] = e; si[j] = j;
    __syncthreads();
    for (int s = 64; s > 0; s >>= 1) {
        if (j < s) {
            float vb = sv[j + s]; int ib = si[j + s];
            if (vb > sv[j] || (vb == sv[j] && ib < si[j])) { sv[j] = vb; si[j] = ib; }
        }
        __syncthreads();
    }
    if (j == 0) { g_rowmax_d[i] = sv[0]; g_rowarg_d[i] = si[0]; }
    __syncthreads();

    // --- row argmax for feat ---
    sv[j] = acc; si[j] = j;
    __syncthreads();
    for (int s = 64; s > 0; s >>= 1) {
        if (j < s) {
            float vb = sv[j + s]; int ib = si[j + s];
            if (vb > sv[j] || (vb == sv[j] && ib < si[j])) { sv[j] = vb; si[j] = ib; }
        }
        __syncthreads();
    }
    if (j == 0) { g_rowmax_f[i] = sv[0]; g_rowarg_f[i] = si[0]; }
}

// ============ K3: column argmax, gathers, two stable sorts, geo vector ========
// 1 block, 256 threads
__global__ void k_assemble() {
    int t = threadIdx.x;
    __shared__ float cmd[128]; __shared__ int cad[128];
    __shared__ float cmf[128]; __shared__ int caf[128];
    __shared__ float md[256], fs[256], mf[256], mdist[256];
    __shared__ unsigned long long key[256];

    if (t < 128) {
        float bd = -1e30f; int bdi = 0;
        float bf = -1e30f; int bfi = 0;
        for (int i = 0; i < 128; i++) {
            float vd = g_dist[i * 128 + t];
            if (vd > bd) { bd = vd; bdi = i; }
            float vf = g_feat[i * 128 + t];
            if (vf > bf) { bf = vf; bfi = i; }
        }
        cmd[t] = bd; cad[t] = bdi;
        cmf[t] = bf; caf[t] = bfi;
    }
    __syncthreads();

    if (t < 128) {
        md[t]    = g_rowmax_d[t];
        fs[t]    = g_feat[t * 128 + g_rowarg_d[t]];
        mf[t]    = g_rowmax_f[t];
        mdist[t] = g_dist[t * 128 + g_rowarg_f[t]];
    } else {
        int j = t - 128;
        md[t]    = cmd[j];
        fs[t]    = g_feat[cad[j] * 128 + j];
        mf[t]    = cmf[j];
        mdist[t] = g_dist[caf[j] * 128 + j];
    }
    __syncthreads();

    // ---- sort 1: stable argsort(-min_dist) ----
    key[t] = sort_key(md[t], t);
    for (int k = 2; k <= 256; k <<= 1) {
        for (int j = k >> 1; j > 0; j >>= 1) {
            __syncthreads();
            int ixj = t ^ j;
            if (ixj > t) {
                bool dirAsc = ((t & k) == 0);
                unsigned long long a = key[t], b = key[ixj];
                if ((a > b) == dirAsc) { key[t] = b; key[ixj] = a; }
            }
        }
    }
    __syncthreads();
    {
        unsigned long long K = ~key[t];
        int idx = 255 - (int)(K & 0xFFFFFFFFull);
        g_geo[t] = md[idx] * fs[idx];
    }

    // ---- sort 2: stable argsort(-match_feat) ----
    key[t] = sort_key(mf[t], t);
    for (int k = 2; k <= 256; k <<= 1) {
        for (int j = k >> 1; j > 0; j >>= 1) {
            __syncthreads();
            int ixj = t ^ j;
            if (ixj > t) {
                bool dirAsc = ((t & k) == 0);
                unsigned long long a = key[t], b = key[ixj];
                if ((a > b) == dirAsc) { key[t] = b; key[ixj] = a; }
            }
        }
    }
    __syncthreads();
    {
        unsigned long long K = ~key[t];
        int idx = 255 - (int)(K & 0xFFFFFFFFull);
        g_geo[256 + t] = mdist[idx] * mf[idx];
    }
}

// ================ K4: layer1 (512 -> 256), parallel across SMs ===============
// grid 64, block 128: one warp per output channel
__global__ void k_fc1(const float* __restrict__ W1, const float* __restrict__ b1) {
    int w = threadIdx.x >> 5;
    int lane = threadIdx.x & 31;
    int c = blockIdx.x * 4 + w;
    const float* row = W1 + (size_t)c * 512;
    float acc = 0.0f;
#pragma unroll 4
    for (int k = lane; k < 512; k += 32) acc += row[k] * g_geo[k];
#pragma unroll
    for (int o = 16; o > 0; o >>= 1) acc += __shfl_down_sync(0xffffffffu, acc, o);
    if (lane == 0) g_h1[c] = acc + b1[c];
}

// ======== K5: GN1+ReLU, layer2, GN2+ReLU, layer3 -> output (1 block) =========
__global__ void k_tail(const float* __restrict__ W2, const float* __restrict__ b2,
                       const float* __restrict__ gm1, const float* __restrict__ bt1,
                       const float* __restrict__ gm2, const float* __restrict__ bt2,
                       const float* __restrict__ W3, const float* __restrict__ b3,
                       float* __restrict__ out) {
    __shared__ float ha[256];
    __shared__ float h2[128];
    __shared__ float h2a[128];
    int t = threadIdx.x;
    int w = t >> 5;
    int lane = t & 31;

    // GroupNorm1: 8 groups x 32 channels == one warp per group
    {
        float x = g_h1[t];
        float s = x;
#pragma unroll
        for (int o = 16; o > 0; o >>= 1) s += __shfl_xor_sync(0xffffffffu, s, o);
        float mean = s / 32.0f;
        float e = x - mean;
        float v = e * e;
#pragma unroll
        for (int o = 16; o > 0; o >>= 1) v += __shfl_xor_sync(0xffffffffu, v, o);
        v /= 32.0f;
        float xn = e / sqrtf(v + 1e-5f) * gm1[t] + bt1[t];
        ha[t] = fmaxf(xn, 0.0f);
    }
    __syncthreads();

    // layer2: 128 outputs, warp-per-output (16 per warp)
    for (int c = w; c < 128; c += 8) {
        const float* row = W2 + (size_t)c * 256;
        float acc = 0.0f;
#pragma unroll 2
        for (int k = lane; k < 256; k += 32) acc += row[k] * ha[k];
#pragma unroll
        for (int o = 16; o > 0; o >>= 1) acc += __shfl_xor_sync(0xffffffffu, acc, o);
        if (lane == 0) h2[c] = acc + b2[c];
    }
    __syncthreads();

    // GroupNorm2: 8 groups x 16 channels (half-warp reductions in warps 0..3)
    if (t < 128) {
        float x = h2[t];
        float s = x;
#pragma unroll
        for (int o = 8; o > 0; o >>= 1) s += __shfl_xor_sync(0xffffffffu, s, o);
        float mean = s / 16.0f;
        float e = x - mean;
        float v = e * e;
#pragma unroll
        for (int o = 8; o > 0; o >>= 1) v += __shfl_xor_sync(0xffffffffu, v, o);
        v /= 16.0f;
        float xn = e / sqrtf(v + 1e-5f) * gm2[t] + bt2[t];
        h2a[t] = fmaxf(xn, 0.0f);
    }
    __syncthreads();

    // layer3: 2 outputs
    if (w < 2) {
        const float* row = W3 + (size_t)w * 128;
        float acc = 0.0f;
#pragma unroll
        for (int k = lane; k < 128; k += 32) acc += row[k] * h2a[k];
#pragma unroll
        for (int o = 16; o > 0; o >>= 1) acc += __shfl_xor_sync(0xffffffffu, acc, o);
        if (lane == 0) out[w] = acc + b3[w];
    }
}

extern "C" void kernel_launch(void* const* d_in, const int* in_sizes, int n_in,
                              void* d_out, int out_size) {
    const float* pts   = (const float*)d_in[0];
    const float* reff  = (const float*)d_in[1];
    const float* srcf  = (const float*)d_in[2];
    const float* trans = (const float*)d_in[3];
    const float* W1 = (const float*)d_in[4];
    const float* b1 = (const float*)d_in[5];
    const float* g1 = (const float*)d_in[6];
    const float* bt1 = (const float*)d_in[7];
    const float* W2 = (const float*)d_in[8];
    const float* b2 = (const float*)d_in[9];
    const float* g2 = (const float*)d_in[10];
    const float* bt2 = (const float*)d_in[11];
    const float* W3 = (const float*)d_in[12];
    const float* b3 = (const float*)d_in[13];

    k_normalize<<<1, 256>>>(pts, trans);
    k_rows<<<128, 128>>>(reff, srcf);
    k_assemble<<<1, 256>>>();
    k_fc1<<<64, 128>>>(W1, b1);
    k_tail<<<1, 256>>>(W2, b2, g1, bt1, g2, bt2, W3, b3, (float*)d_out);
}

// round 2
// speedup vs baseline: 1.1474x; 1.1474x over previous
#include <cuda_runtime.h>
#include <math.h>

// Problem dims (fixed by setup_inputs)
#define NREF 128
#define NSRC 128
#define FD   256

// -------- device scratch (no allocations allowed) --------
__device__ float g_dist[NREF * NSRC];
__device__ float g_feat[NREF * NSRC];
__device__ float g_md[NREF];      // row max of dist
__device__ float g_fs[NREF];      // feat at dist-argmax column
__device__ float g_mf[NREF];      // row max of feat
__device__ float g_mdist[NREF];   // dist at feat-argmax column

// orderable uint mapping: ascending uint <=> ascending float
__device__ __forceinline__ unsigned int f2o(float f) {
    unsigned int u = __float_as_uint(f);
    return (u & 0x80000000u) ? ~u : (u | 0x80000000u);
}
// composite sort key: descending value, ascending index (stable argsort of -v)
// complemented so ASCENDING uint64 sort gives that order.
__device__ __forceinline__ unsigned long long sort_key(float v, int idx) {
    unsigned long long K =
        ((unsigned long long)f2o(v) << 32) | (unsigned long long)(255 - idx);
    return ~K;
}

// ===================== KA: normalize (redundant) + rows ======================
// grid 128 (one block per ref row i), 128 threads (one per src col j)
__global__ void k_rows(const float* __restrict__ pts,
                       const float* __restrict__ trans,
                       const float* __restrict__ ref_f,
                       const float* __restrict__ src_f) {
    __shared__ float spx[256], spy[256], spz[256], ssq[256];
    __shared__ __align__(16) float sref[FD];
    __shared__ float sred[12];
    __shared__ float sdrow[128];   // dist row (exp values)
    __shared__ float sfrow[128];   // feat row
    __shared__ float sv[128];
    __shared__ int   si[128];
    __shared__ int   s_argd, s_argf;

    int t = threadIdx.x;
    int i = blockIdx.x;
    int w = t >> 5, lane = t & 31;

    // prefetch ref feature row into shared (independent of point math)
    sref[t]       = ref_f[i * FD + t];
    sref[t + 128] = ref_f[i * FD + 128 + t];

    // load transform (rows 0..2 of the 4x4, row-major)
    float tr0 = trans[0], tr1 = trans[1], tr2  = trans[2],  tr3  = trans[3];
    float tr4 = trans[4], tr5 = trans[5], tr6  = trans[6],  tr7  = trans[7];
    float tr8 = trans[8], tr9 = trans[9], tr10 = trans[10], tr11 = trans[11];

    // ---- load 2 points/thread, transform src half, accumulate sums ----
    float lx = 0.f, ly = 0.f, lz = 0.f;
#pragma unroll
    for (int rr = 0; rr < 2; rr++) {
        int k = t + rr * 128;
        float px = pts[3 * k + 0];
        float py = pts[3 * k + 1];
        float pz = pts[3 * k + 2];
        if (k >= 128) {
            float x = tr0 * px + tr1 * py + tr2  * pz + tr3;
            float y = tr4 * px + tr5 * py + tr6  * pz + tr7;
            float z = tr8 * px + tr9 * py + tr10 * pz + tr11;
            px = x; py = y; pz = z;
        }
        spx[k] = px; spy[k] = py; spz[k] = pz;
        lx += px; ly += py; lz += pz;
    }
#pragma unroll
    for (int o = 16; o > 0; o >>= 1) {
        lx += __shfl_xor_sync(0xffffffffu, lx, o);
        ly += __shfl_xor_sync(0xffffffffu, ly, o);
        lz += __shfl_xor_sync(0xffffffffu, lz, o);
    }
    if (lane == 0) { sred[w] = lx; sred[4 + w] = ly; sred[8 + w] = lz; }
    __syncthreads();
    float cx = (sred[0] + sred[1] + sred[2]  + sred[3])  * (1.0f / 256.0f);
    float cy = (sred[4] + sred[5] + sred[6]  + sred[7])  * (1.0f / 256.0f);
    float cz = (sred[8] + sred[9] + sred[10] + sred[11]) * (1.0f / 256.0f);

    // ---- center, compute sq norms, find max ----
    float lm = 0.f;
#pragma unroll
    for (int rr = 0; rr < 2; rr++) {
        int k = t + rr * 128;
        float px = spx[k] - cx;
        float py = spy[k] - cy;
        float pz = spz[k] - cz;
        float s = px * px + py * py + pz * pz;
        spx[k] = px; spy[k] = py; spz[k] = pz; ssq[k] = s;
        lm = fmaxf(lm, s);
    }
#pragma unroll
    for (int o = 16; o > 0; o >>= 1)
        lm = fmaxf(lm, __shfl_xor_sync(0xffffffffu, lm, o));
    __syncthreads();   // protect sred reuse
    if (lane == 0) sred[w] = lm;
    __syncthreads();
    float m2  = fmaxf(fmaxf(sred[0], sred[1]), fmaxf(sred[2], sred[3]));
    float inv = 1.0f / sqrtf(m2);
    float inv2 = inv * inv;
#pragma unroll
    for (int rr = 0; rr < 2; rr++) {
        int k = t + rr * 128;
        spx[k] *= inv; spy[k] *= inv; spz[k] *= inv;
        ssq[k] *= inv2;
    }
    __syncthreads();

    // ---- dist entry for (i, j=t) ----
    float rx = spx[i], ry = spy[i], rz = spz[i], rs = ssq[i];
    int sj = 128 + t;
    float d = rs + ssq[sj] - 2.0f * (rx * spx[sj] + ry * spy[sj] + rz * spz[sj]);
    d = fmaxf(d, 0.0f);
    float e = expf(-d);
    g_dist[i * 128 + t] = e;
    sdrow[t] = e;

    // ---- feat entry: dot(ref_i, src_j), K=256, float4 ----
    const float4* s4 = reinterpret_cast<const float4*>(src_f + (size_t)t * FD);
    const float4* r4 = reinterpret_cast<const float4*>(sref);
    float acc = 0.0f;
#pragma unroll 8
    for (int k = 0; k < FD / 4; k++) {
        float4 v = s4[k];
        float4 r = r4[k];
        acc += r.x * v.x + r.y * v.y + r.z * v.z + r.w * v.w;
    }
    g_feat[i * 128 + t] = acc;
    sfrow[t] = acc;

    // ---- row argmax (first occurrence) for dist ----
    sv[t] = e; si[t] = t;
    __syncthreads();
    for (int s = 64; s > 0; s >>= 1) {
        if (t < s) {
            float vb = sv[t + s]; int ib = si[t + s];
            if (vb > sv[t] || (vb == sv[t] && ib < si[t])) { sv[t] = vb; si[t] = ib; }
        }
        __syncthreads();
    }
    if (t == 0) { g_md[i] = sv[0]; s_argd = si[0]; }
    __syncthreads();

    // ---- row argmax for feat ----
    sv[t] = acc; si[t] = t;
    __syncthreads();
    for (int s = 64; s > 0; s >>= 1) {
        if (t < s) {
            float vb = sv[t + s]; int ib = si[t + s];
            if (vb > sv[t] || (vb == sv[t] && ib < si[t])) { sv[t] = vb; si[t] = ib; }
        }
        __syncthreads();
    }
    if (t == 0) {
        g_mf[i]    = sv[0];
        g_fs[i]    = sfrow[s_argd];   // feat at dist-argmax
        g_mdist[i] = sdrow[si[0]];    // dist at feat-argmax
    }
}

// ========== KB: col argmax + sorts + full MLP, single block, 512 thr =========
__global__ void __launch_bounds__(512)
k_tail(const float* __restrict__ W1, const float* __restrict__ b1,
       const float* __restrict__ gm1, const float* __restrict__ bt1,
       const float* __restrict__ W2, const float* __restrict__ b2,
       const float* __restrict__ gm2, const float* __restrict__ bt2,
       const float* __restrict__ W3, const float* __restrict__ b3,
       float* __restrict__ out) {
    __shared__ float scv[512];
    __shared__ int   sci[512];
    __shared__ float md[256], fs[256], mf[256], mdist[256];
    __shared__ unsigned long long key[256];
    __shared__ __align__(16) float s_geo[512];
    __shared__ __align__(16) float ha[256];
    __shared__ float h1s[256];
    __shared__ float h2s[128];
    __shared__ __align__(16) float h2a[128];

    int t = threadIdx.x;
    int w = t >> 5, lane = t & 31;

    // ---- column argmax: 4 groups of 128 threads, each a 64-row strip ----
    {
        int g = t >> 7;           // 0: dist lo, 1: dist hi, 2: feat lo, 3: feat hi
        int c = t & 127;
        const float* M = (g < 2) ? g_dist : g_feat;
        int ibase = (g & 1) * 64;
        float bv = -1e30f; int bi = ibase;
#pragma unroll 8
        for (int ii = 0; ii < 64; ii++) {
            float v = M[(ibase + ii) * 128 + c];
            if (v > bv) { bv = v; bi = ibase + ii; }
        }
        scv[t] = bv; sci[t] = bi;
    }
    __syncthreads();

    // ---- assemble the four 256-vectors ----
    if (t < 256) {
        if (t < 128) {
            md[t]    = g_md[t];
            fs[t]    = g_fs[t];
            mf[t]    = g_mf[t];
            mdist[t] = g_mdist[t];
        } else {
            int c = t - 128;
            float a = scv[c],       b = scv[128 + c];
            int   ia = sci[c],      ib = sci[128 + c];
            float cmv = (b > a) ? b : a;
            int   cmi = (b > a) ? ib : ia;
            md[t] = cmv;
            fs[t] = g_feat[cmi * 128 + c];
            float af = scv[256 + c], bf = scv[384 + c];
            int   iaf = sci[256 + c], ibf = sci[384 + c];
            float cfv = (bf > af) ? bf : af;
            int   cfi = (bf > af) ? ibf : iaf;
            mf[t]    = cfv;
            mdist[t] = g_dist[cfi * 128 + c];
        }
    }
    __syncthreads();

    // ---- sort 1: stable argsort(-min_dist) ----
    if (t < 256) key[t] = sort_key(md[t], t);
    for (int k = 2; k <= 256; k <<= 1) {
        for (int j = k >> 1; j > 0; j >>= 1) {
            __syncthreads();
            if (t < 256) {
                int ixj = t ^ j;
                if (ixj > t) {
                    bool dirAsc = ((t & k) == 0);
                    unsigned long long a = key[t], b = key[ixj];
                    if ((a > b) == dirAsc) { key[t] = b; key[ixj] = a; }
                }
            }
        }
    }
    __syncthreads();
    if (t < 256) {
        int idx = 255 - (int)(~key[t] & 0xFFFFFFFFull);
        s_geo[t] = md[idx] * fs[idx];
    }
    __syncthreads();

    // ---- sort 2: stable argsort(-match_feat) ----
    if (t < 256) key[t] = sort_key(mf[t], t);
    for (int k = 2; k <= 256; k <<= 1) {
        for (int j = k >> 1; j > 0; j >>= 1) {
            __syncthreads();
            if (t < 256) {
                int ixj = t ^ j;
                if (ixj > t) {
                    bool dirAsc = ((t & k) == 0);
                    unsigned long long a = key[t], b = key[ixj];
                    if ((a > b) == dirAsc) { key[t] = b; key[ixj] = a; }
                }
            }
        }
    }
    __syncthreads();
    if (t < 256) {
        int idx = 255 - (int)(~key[t] & 0xFFFFFFFFull);
        s_geo[256 + t] = mdist[idx] * mf[idx];
    }
    __syncthreads();

    // ---- fc1: 512 -> 256, 16 warps x 16 channels, float4 ----
    const float4* geo4 = reinterpret_cast<const float4*>(s_geo);
    for (int c = w; c < 256; c += 16) {
        const float4* row = reinterpret_cast<const float4*>(W1 + (size_t)c * 512);
        float acc = 0.0f;
#pragma unroll
        for (int q = 0; q < 4; q++) {
            float4 a = row[lane + 32 * q];
            float4 g = geo4[lane + 32 * q];
            acc += a.x * g.x + a.y * g.y + a.z * g.z + a.w * g.w;
        }
#pragma unroll
        for (int o = 16; o > 0; o >>= 1)
            acc += __shfl_xor_sync(0xffffffffu, acc, o);
        if (lane == 0) h1s[c] = acc + b1[c];
    }
    __syncthreads();

    // ---- GroupNorm1 (8 groups x 32) + ReLU ----
    if (t < 256) {
        float x = h1s[t];
        float s = x;
#pragma unroll
        for (int o = 16; o > 0; o >>= 1) s += __shfl_xor_sync(0xffffffffu, s, o);
        float mean = s * (1.0f / 32.0f);
        float e = x - mean;
        float v = e * e;
#pragma unroll
        for (int o = 16; o > 0; o >>= 1) v += __shfl_xor_sync(0xffffffffu, v, o);
        v *= (1.0f / 32.0f);
        float xn = e / sqrtf(v + 1e-5f) * gm1[t] + bt1[t];
        ha[t] = fmaxf(xn, 0.0f);
    }
    __syncthreads();

    // ---- fc2: 256 -> 128, 16 warps x 8 channels ----
    const float4* ha4 = reinterpret_cast<const float4*>(ha);
    for (int c = w; c < 128; c += 16) {
        const float4* row = reinterpret_cast<const float4*>(W2 + (size_t)c * 256);
        float acc = 0.0f;
#pragma unroll
        for (int q = 0; q < 2; q++) {
            float4 a = row[lane + 32 * q];
            float4 g = ha4[lane + 32 * q];
            acc += a.x * g.x + a.y * g.y + a.z * g.z + a.w * g.w;
        }
#pragma unroll
        for (int o = 16; o > 0; o >>= 1)
            acc += __shfl_xor_sync(0xffffffffu, acc, o);
        if (lane == 0) h2s[c] = acc + b2[c];
    }
    __syncthreads();

    // ---- GroupNorm2 (8 groups x 16) + ReLU ----
    if (t < 128) {
        float x = h2s[t];
        float s = x;
#pragma unroll
        for (int o = 8; o > 0; o >>= 1) s += __shfl_xor_sync(0xffffffffu, s, o);
        float mean = s * (1.0f / 16.0f);
        float e = x - mean;
        float v = e * e;
#pragma unroll
        for (int o = 8; o > 0; o >>= 1) v += __shfl_xor_sync(0xffffffffu, v, o);
        v *= (1.0f / 16.0f);
        float xn = e / sqrtf(v + 1e-5f) * gm2[t] + bt2[t];
        h2a[t] = fmaxf(xn, 0.0f);
    }
    __syncthreads();

    // ---- fc3: 128 -> 2 ----
    if (w < 2) {
        const float4* row = reinterpret_cast<const float4*>(W3 + (size_t)w * 128);
        float4 a = row[lane];
        float4 g = reinterpret_cast<const float4*>(h2a)[lane];
        float acc = a.x * g.x + a.y * g.y + a.z * g.z + a.w * g.w;
#pragma unroll
        for (int o = 16; o > 0; o >>= 1)
            acc += __shfl_xor_sync(0xffffffffu, acc, o);
        if (lane == 0) out[w] = acc + b3[w];
    }
}

extern "C" void kernel_launch(void* const* d_in, const int* in_sizes, int n_in,
                              void* d_out, int out_size) {
    const float* pts   = (const float*)d_in[0];
    const float* reff  = (const float*)d_in[1];
    const float* srcf  = (const float*)d_in[2];
    const float* trans = (const float*)d_in[3];
    const float* W1 = (const float*)d_in[4];
    const float* b1 = (const float*)d_in[5];
    const float* g1 = (const float*)d_in[6];
    const float* bt1 = (const float*)d_in[7];
    const float* W2 = (const float*)d_in[8];
    const float* b2 = (const float*)d_in[9];
    const float* g2 = (const float*)d_in[10];
    const float* bt2 = (const float*)d_in[11];
    const float* W3 = (const float*)d_in[12];
    const float* b3 = (const float*)d_in[13];

    k_rows<<<128, 128>>>(pts, trans, reff, srcf);
    k_tail<<<1, 512>>>(W1, b1, g1, bt1, W2, b2, g2, bt2, W3, b3, (float*)d_out);
}

// round 3
// speedup vs baseline: 1.8991x; 1.6552x over previous
#include <cuda_runtime.h>
#include <math.h>

#define NREF 128
#define FD   256

// -------- device scratch (no allocations allowed; zero-initialized) --------
__device__ float g_dist[NREF * NREF];
__device__ float g_feat[NREF * NREF];
__device__ float g_md[NREF];      // row max of dist
__device__ float g_fs[NREF];      // feat at dist-argmax column
__device__ float g_mf[NREF];      // row max of feat
__device__ float g_mdist[NREF];   // dist at feat-argmax column
__device__ unsigned long long g_colkey_d[NREF];  // packed col argmax (dist)
__device__ unsigned long long g_colkey_f[NREF];  // packed col argmax (feat)

// orderable uint mapping: ascending uint <=> ascending float
__device__ __forceinline__ unsigned int f2o(float f) {
    unsigned int u = __float_as_uint(f);
    return (u & 0x80000000u) ? ~u : (u | 0x80000000u);
}
// packed key: max over keys == max value, ties -> smallest index
__device__ __forceinline__ unsigned long long pk(float v, unsigned inv_idx) {
    return (((unsigned long long)f2o(v)) << 32) | (unsigned long long)inv_idx;
}

// ===================== KA: normalize (redundant) + one row per block =========
__global__ void __launch_bounds__(128)
k_rows(const float* __restrict__ pts, const float* __restrict__ trans,
       const float* __restrict__ ref_f, const float* __restrict__ src_f) {
    __shared__ float spx[256], spy[256], spz[256], ssq[256];
    __shared__ __align__(16) float sref[FD];
    __shared__ float sdrow[128], sfrow[128];
    __shared__ float sred[12], smax[4];
    __shared__ unsigned long long swd[4], swf[4];

    int t = threadIdx.x;
    int i = blockIdx.x;
    int w = t >> 5, lane = t & 31;

    // ref feature row -> shared
    sref[t]       = __ldg(&ref_f[i * FD + t]);
    sref[t + 128] = __ldg(&ref_f[i * FD + 128 + t]);

    float tr0 = __ldg(&trans[0]), tr1 = __ldg(&trans[1]), tr2  = __ldg(&trans[2]),  tr3  = __ldg(&trans[3]);
    float tr4 = __ldg(&trans[4]), tr5 = __ldg(&trans[5]), tr6  = __ldg(&trans[6]),  tr7  = __ldg(&trans[7]);
    float tr8 = __ldg(&trans[8]), tr9 = __ldg(&trans[9]), tr10 = __ldg(&trans[10]), tr11 = __ldg(&trans[11]);

    // ---- load 2 points/thread, transform src half, sum for centroid ----
    float lx = 0.f, ly = 0.f, lz = 0.f;
#pragma unroll
    for (int rr = 0; rr < 2; rr++) {
        int k = t + rr * 128;
        float px = pts[3 * k + 0];
        float py = pts[3 * k + 1];
        float pz = pts[3 * k + 2];
        if (k >= 128) {
            float x = tr0 * px + tr1 * py + tr2  * pz + tr3;
            float y = tr4 * px + tr5 * py + tr6  * pz + tr7;
            float z = tr8 * px + tr9 * py + tr10 * pz + tr11;
            px = x; py = y; pz = z;
        }
        spx[k] = px; spy[k] = py; spz[k] = pz;
        lx += px; ly += py; lz += pz;
    }
#pragma unroll
    for (int o = 16; o > 0; o >>= 1) {
        lx += __shfl_xor_sync(0xffffffffu, lx, o);
        ly += __shfl_xor_sync(0xffffffffu, ly, o);
        lz += __shfl_xor_sync(0xffffffffu, lz, o);
    }
    if (lane == 0) { sred[w] = lx; sred[4 + w] = ly; sred[8 + w] = lz; }
    __syncthreads();
    float cx = (sred[0] + sred[1] + sred[2]  + sred[3])  * (1.0f / 256.0f);
    float cy = (sred[4] + sred[5] + sred[6]  + sred[7])  * (1.0f / 256.0f);
    float cz = (sred[8] + sred[9] + sred[10] + sred[11]) * (1.0f / 256.0f);

    float lm = 0.f;
#pragma unroll
    for (int rr = 0; rr < 2; rr++) {
        int k = t + rr * 128;
        float px = spx[k] - cx;
        float py = spy[k] - cy;
        float pz = spz[k] - cz;
        float s = px * px + py * py + pz * pz;
        spx[k] = px; spy[k] = py; spz[k] = pz; ssq[k] = s;
        lm = fmaxf(lm, s);
    }
#pragma unroll
    for (int o = 16; o > 0; o >>= 1)
        lm = fmaxf(lm, __shfl_xor_sync(0xffffffffu, lm, o));
    if (lane == 0) smax[w] = lm;
    __syncthreads();
    float m2  = fmaxf(fmaxf(smax[0], smax[1]), fmaxf(smax[2], smax[3]));
    float inv = 1.0f / sqrtf(m2);
    float inv2 = inv * inv;
#pragma unroll
    for (int rr = 0; rr < 2; rr++) {
        int k = t + rr * 128;
        spx[k] *= inv; spy[k] *= inv; spz[k] *= inv;
        ssq[k] *= inv2;
    }
    __syncthreads();

    // ---- dist entry for (i, j=t) ----
    float rx = spx[i], ry = spy[i], rz = spz[i], rs = ssq[i];
    int sj = 128 + t;
    float d = rs + ssq[sj] - 2.0f * (rx * spx[sj] + ry * spy[sj] + rz * spz[sj]);
    d = fmaxf(d, 0.0f);
    float e = expf(-d);
    g_dist[i * 128 + t] = e;
    sdrow[t] = e;
    atomicMax(&g_colkey_d[t], pk(e, 127u - (unsigned)i));

    // ---- feat row: warp-cooperative coalesced dots (32 rows per warp) ----
    {
        const float4* sr4 = reinterpret_cast<const float4*>(sref);
        float4 r0 = sr4[lane];
        float4 r1 = sr4[lane + 32];
        int jbase = w * 32;
#pragma unroll 4
        for (int jj = 0; jj < 32; jj++) {
            int j = jbase + jj;
            const float4* s4 = reinterpret_cast<const float4*>(src_f + (size_t)j * FD);
            float4 a0 = __ldg(&s4[lane]);
            float4 a1 = __ldg(&s4[lane + 32]);
            float acc = a0.x * r0.x + a0.y * r0.y + a0.z * r0.z + a0.w * r0.w
                      + a1.x * r1.x + a1.y * r1.y + a1.z * r1.z + a1.w * r1.w;
#pragma unroll
            for (int o = 16; o > 0; o >>= 1)
                acc += __shfl_xor_sync(0xffffffffu, acc, o);
            if (lane == 0) sfrow[j] = acc;
        }
    }
    __syncthreads();
    float fv = sfrow[t];
    g_feat[i * 128 + t] = fv;
    atomicMax(&g_colkey_f[t], pk(fv, 127u - (unsigned)i));

    // ---- row argmaxes via packed warp reduction ----
    unsigned long long kd = pk(e,  127u - (unsigned)t);
    unsigned long long kf = pk(fv, 127u - (unsigned)t);
#pragma unroll
    for (int o = 16; o > 0; o >>= 1) {
        unsigned long long od = __shfl_xor_sync(0xffffffffu, kd, o);
        unsigned long long of = __shfl_xor_sync(0xffffffffu, kf, o);
        if (od > kd) kd = od;
        if (of > kf) kf = of;
    }
    if (lane == 0) { swd[w] = kd; swf[w] = kf; }
    __syncthreads();
    if (t == 0) {
        unsigned long long bd = swd[0], bf = swf[0];
#pragma unroll
        for (int q = 1; q < 4; q++) {
            if (swd[q] > bd) bd = swd[q];
            if (swf[q] > bf) bf = swf[q];
        }
        int jd = 127 - (int)(bd & 0xFFFFFFFFull);
        int jf = 127 - (int)(bf & 0xFFFFFFFFull);
        g_md[i]    = sdrow[jd];
        g_fs[i]    = sfrow[jd];
        g_mf[i]    = sfrow[jf];
        g_mdist[i] = sdrow[jf];
    }
}

// ========== KB: assemble + rank-permute + full MLP, 1 block x 512 ============
__global__ void __launch_bounds__(512)
k_tail(const float* __restrict__ W1, const float* __restrict__ b1,
       const float* __restrict__ gm1, const float* __restrict__ bt1,
       const float* __restrict__ W2, const float* __restrict__ b2,
       const float* __restrict__ gm2, const float* __restrict__ bt2,
       const float* __restrict__ W3, const float* __restrict__ b3,
       float* __restrict__ out) {
    __shared__ float smd[256], sfs[256], smf[256], smdist[256];
    __shared__ unsigned long long skey[512];
    __shared__ __align__(16) float s_geo[512];
    __shared__ float h1s[256];
    __shared__ __align__(16) float ha[256];
    __shared__ float h2s[128];
    __shared__ __align__(16) float h2a[128];

    int t = threadIdx.x;
    int w = t >> 5, lane = t & 31;

    // ---- assemble the four 256-vectors ----
    if (t < 128) {
        smd[t]    = g_md[t];
        sfs[t]    = g_fs[t];
        smf[t]    = g_mf[t];
        smdist[t] = g_mdist[t];
    } else if (t < 256) {
        int c = t - 128;
        unsigned long long kd = g_colkey_d[c];
        unsigned long long kf = g_colkey_f[c];
        int id = 127 - (int)(kd & 0xFFFFFFFFull);
        int jf = 127 - (int)(kf & 0xFFFFFFFFull);
        smd[t]    = g_dist[id * 128 + c];
        sfs[t]    = g_feat[id * 128 + c];
        smf[t]    = g_feat[jf * 128 + c];
        smdist[t] = g_dist[jf * 128 + c];
    }
    __syncthreads();

    // ---- sort keys: threads 0-255 -> sort1 (min_dist), 256-511 -> sort2 ----
    unsigned long long mykey;
    if (t < 256) mykey = pk(smd[t], 255u - (unsigned)t);
    else         mykey = pk(smf[t - 256], 255u - (unsigned)(t - 256));
    skey[t] = mykey;
    __syncthreads();

    // reset col keys for the next graph replay (overlaps with rank work below
    // on other warps; values already consumed into shared above)
    // ---- rank computation: pos = #{j : key_j > mykey} (unique keys) ----
    int base = (t < 256) ? 0 : 256;
    int r = 0;
#pragma unroll 16
    for (int j = 0; j < 256; j++)
        r += (skey[base + j] > mykey) ? 1 : 0;
    if (t < 256) s_geo[r]       = smd[t] * sfs[t];
    else         s_geo[256 + r] = smdist[t - 256] * smf[t - 256];
    if (t < 128)           g_colkey_d[t] = 0ull;
    else if (t < 256)      g_colkey_f[t - 128] = 0ull;
    __syncthreads();

    // ---- fc1: 512 -> 256, 16 warps x 16 contiguous channels ----
    const float4* geo4 = reinterpret_cast<const float4*>(s_geo);
    float4 g0 = geo4[lane], g1v = geo4[lane + 32], g2v = geo4[lane + 64], g3v = geo4[lane + 96];
#pragma unroll 4
    for (int cc = 0; cc < 16; cc++) {
        int c = (w << 4) | cc;
        const float4* row = reinterpret_cast<const float4*>(W1 + (size_t)c * 512);
        float4 a0 = __ldg(&row[lane]);
        float4 a1 = __ldg(&row[lane + 32]);
        float4 a2 = __ldg(&row[lane + 64]);
        float4 a3 = __ldg(&row[lane + 96]);
        float acc = a0.x * g0.x + a0.y * g0.y + a0.z * g0.z + a0.w * g0.w
                  + a1.x * g1v.x + a1.y * g1v.y + a1.z * g1v.z + a1.w * g1v.w
                  + a2.x * g2v.x + a2.y * g2v.y + a2.z * g2v.z + a2.w * g2v.w
                  + a3.x * g3v.x + a3.y * g3v.y + a3.z * g3v.z + a3.w * g3v.w;
#pragma unroll
        for (int o = 16; o > 0; o >>= 1)
            acc += __shfl_xor_sync(0xffffffffu, acc, o);
        if (lane == 0) h1s[c] = acc + __ldg(&b1[c]);
    }
    __syncthreads();

    // ---- GroupNorm1 (8 groups x 32 = warp per group) + ReLU ----
    if (t < 256) {
        float x = h1s[t];
        float s = x;
#pragma unroll
        for (int o = 16; o > 0; o >>= 1) s += __shfl_xor_sync(0xffffffffu, s, o);
        float mean = s * (1.0f / 32.0f);
        float e = x - mean;
        float v = e * e;
#pragma unroll
        for (int o = 16; o > 0; o >>= 1) v += __shfl_xor_sync(0xffffffffu, v, o);
        v *= (1.0f / 32.0f);
        float xn = e / sqrtf(v + 1e-5f) * __ldg(&gm1[t]) + __ldg(&bt1[t]);
        ha[t] = fmaxf(xn, 0.0f);
    }
    __syncthreads();

    // ---- fc2: 256 -> 128, 16 warps x 8 contiguous channels ----
    const float4* ha4 = reinterpret_cast<const float4*>(ha);
    float4 hv0 = ha4[lane], hv1 = ha4[lane + 32];
#pragma unroll 4
    for (int cc = 0; cc < 8; cc++) {
        int c = (w << 3) | cc;
        const float4* row = reinterpret_cast<const float4*>(W2 + (size_t)c * 256);
        float4 a0 = __ldg(&row[lane]);
        float4 a1 = __ldg(&row[lane + 32]);
        float acc = a0.x * hv0.x + a0.y * hv0.y + a0.z * hv0.z + a0.w * hv0.w
                  + a1.x * hv1.x + a1.y * hv1.y + a1.z * hv1.z + a1.w * hv1.w;
#pragma unroll
        for (int o = 16; o > 0; o >>= 1)
            acc += __shfl_xor_sync(0xffffffffu, acc, o);
        if (lane == 0) h2s[c] = acc + __ldg(&b2[c]);
    }
    __syncthreads();

    // ---- GroupNorm2 (8 groups x 16 = half-warp per group) + ReLU ----
    if (t < 128) {
        float x = h2s[t];
        float s = x;
#pragma unroll
        for (int o = 8; o > 0; o >>= 1) s += __shfl_xor_sync(0xffffffffu, s, o);
        float mean = s * (1.0f / 16.0f);
        float e = x - mean;
        float v = e * e;
#pragma unroll
        for (int o = 8; o > 0; o >>= 1) v += __shfl_xor_sync(0xffffffffu, v, o);
        v *= (1.0f / 16.0f);
        float xn = e / sqrtf(v + 1e-5f) * __ldg(&gm2[t]) + __ldg(&bt2[t]);
        h2a[t] = fmaxf(xn, 0.0f);
    }
    __syncthreads();

    // ---- fc3: 128 -> 2 ----
    if (w < 2) {
        const float4* row = reinterpret_cast<const float4*>(W3 + (size_t)w * 128);
        float4 a = __ldg(&row[lane]);
        float4 g = reinterpret_cast<const float4*>(h2a)[lane];
        float acc = a.x * g.x + a.y * g.y + a.z * g.z + a.w * g.w;
#pragma unroll
        for (int o = 16; o > 0; o >>= 1)
            acc += __shfl_xor_sync(0xffffffffu, acc, o);
        if (lane == 0) out[w] = acc + __ldg(&b3[w]);
    }
}

extern "C" void kernel_launch(void* const* d_in, const int* in_sizes, int n_in,
                              void* d_out, int out_size) {
    const float* pts   = (const float*)d_in[0];
    const float* reff  = (const float*)d_in[1];
    const float* srcf  = (const float*)d_in[2];
    const float* trans = (const float*)d_in[3];
    const float* W1 = (const float*)d_in[4];
    const float* b1 = (const float*)d_in[5];
    const float* g1 = (const float*)d_in[6];
    const float* bt1 = (const float*)d_in[7];
    const float* W2 = (const float*)d_in[8];
    const float* b2 = (const float*)d_in[9];
    const float* g2 = (const float*)d_in[10];
    const float* bt2 = (const float*)d_in[11];
    const float* W3 = (const float*)d_in[12];
    const float* b3 = (const float*)d_in[13];

    k_rows<<<128, 128>>>(pts, trans, reff, srcf);
    k_tail<<<1, 512>>>(W1, b1, g1, bt1, W2, b2, g2, bt2, W3, b3, (float*)d_out);
}